// round 16
// baseline (speedup 1.0000x reference)
#include <cuda_runtime.h>
#include <cuda_bf16.h>
#include <math.h>
#include <stdint.h>

#define TSTEPS 128
#define NENV   64
#define HID    1024
#define HID3   (3 * HID)
#define GK     3072

#define G      128      // scan CTAs (j-slices of 8)
#define JPC    8

// ---------------- scratch ----------------
__device__ float g_gi[TSTEPS * NENV * HID3];            // 96 MB
__device__ __nv_bfloat16 g_hb[2][NENV * 2048];          // h split: per env [hi(1024) | lo(1024)]
__device__ __align__(16) unsigned g_cnt[8];             // producer-group step counters
__device__ __nv_bfloat16 g_bufA[TSTEPS * NENV * GK];    // split A (x, then ys written by scan)
__device__ __nv_bfloat16 g_bufB[HID3 * GK];             // split B (w_ih, then w_out)

// ---------------- ptx helpers (sm_103-safe) ----------------
__device__ __forceinline__ uint32_t smem_u32(const void* p) {
    uint32_t a;
    asm("{ .reg .u64 t; cvta.to.shared.u64 t, %1; cvt.u32.u64 %0, t; }" : "=r"(a) : "l"(p));
    return a;
}
#define SWZ128(x) ((x) ^ (((x) >> 3) & 0x70))

#define CP16(dst, src) \
    asm volatile("cp.async.cg.shared.global [%0], [%1], 16;" :: "r"(dst), "l"(src))
#define CP_COMMIT() asm volatile("cp.async.commit_group;" ::: "memory")
#define CP_WAIT1()  asm volatile("cp.async.wait_group 1;" ::: "memory")
#define CP_WAIT2()  asm volatile("cp.async.wait_group 2;" ::: "memory")

#define LDSM4(r0, r1, r2, r3, addr) \
    asm volatile("ldmatrix.sync.aligned.m8n8.x4.shared.b16 {%0,%1,%2,%3}, [%4];" \
        : "=r"(r0), "=r"(r1), "=r"(r2), "=r"(r3) : "r"(addr))

#define MMA16816(d, a0, a1, a2, a3, b0, b1) \
    asm volatile("mma.sync.aligned.m16n8k16.row.col.f32.bf16.bf16.f32 " \
        "{%0,%1,%2,%3}, {%4,%5,%6,%7}, {%8,%9}, {%0,%1,%2,%3};" \
        : "+f"((d)[0]), "+f"((d)[1]), "+f"((d)[2]), "+f"((d)[3]) \
        : "r"(a0), "r"(a1), "r"(a2), "r"(a3), "r"(b0), "r"(b1))

__device__ __forceinline__ float sigmoidf_(float x) { return 1.0f / (1.0f + expf(-x)); }

// ---------------- init / copy / split ----------------
__global__ void init_kernel(const float* __restrict__ hxs) {
    int i = blockIdx.x * blockDim.x + threadIdx.x;
    if (i < 8) g_cnt[i] = 0;
    if (i < NENV * HID) {
        float v = hxs[i];
        int env = i >> 10, k = i & 1023;
        __nv_bfloat16 hi = __float2bfloat16(v);
        __nv_bfloat16 lo = __float2bfloat16(v - __bfloat162float(hi));
        g_hb[0][env * 2048 + k] = hi;
        g_hb[0][env * 2048 + 1024 + k] = lo;
    }
}
__global__ void copy_hlast_kernel(float* __restrict__ dst) {
    int i = blockIdx.x * blockDim.x + threadIdx.x;
    if (i < NENV * HID) {
        int env = i >> 10, k = i & 1023;
        dst[i] = __bfloat162float(g_hb[0][env * 2048 + k])
               + __bfloat162float(g_hb[0][env * 2048 + 1024 + k]);
    }
}

// Vectorized split: 8 consecutive k per thread.
// MODE 0 (A operand): [hi, hi, lo]   MODE 1 (B operand): [hi, lo, hi]
template <int MODE>
__global__ void split_bf16(const float* __restrict__ src,
                           __nv_bfloat16* __restrict__ dst, int total8) {
    int i = blockIdx.x * blockDim.x + threadIdx.x;   // one unit = 8 elems
    if (i >= total8) return;
    int m = i >> 7;               // / (HID/8)
    int k8 = (i & 127) * 8;
    const float* s = src + (size_t)m * HID + k8;
    float4 v0 = *(const float4*)s;
    float4 v1 = *(const float4*)(s + 4);
    float f[8] = {v0.x, v0.y, v0.z, v0.w, v1.x, v1.y, v1.z, v1.w};
    unsigned short hi[8], lo[8];
#pragma unroll
    for (int q = 0; q < 8; q++) {
        __nv_bfloat16 h = __float2bfloat16(f[q]);
        hi[q] = *(unsigned short*)&h;
        __nv_bfloat16 l = __float2bfloat16(f[q] - __bfloat162float(h));
        lo[q] = *(unsigned short*)&l;
    }
    uint4 hv, lv;
    hv.x = hi[0] | (hi[1] << 16); hv.y = hi[2] | (hi[3] << 16);
    hv.z = hi[4] | (hi[5] << 16); hv.w = hi[6] | (hi[7] << 16);
    lv.x = lo[0] | (lo[1] << 16); lv.y = lo[2] | (lo[3] << 16);
    lv.z = lo[4] | (lo[5] << 16); lv.w = lo[6] | (lo[7] << 16);
    __nv_bfloat16* row = dst + (size_t)m * GK + k8;
    if (MODE == 0) {
        *(uint4*)&row[0] = hv; *(uint4*)&row[HID] = hv; *(uint4*)&row[2 * HID] = lv;
    } else {
        *(uint4*)&row[0] = hv; *(uint4*)&row[HID] = lv; *(uint4*)&row[2 * HID] = hv;
    }
}

// ---------------- mma.sync bf16 GEMM (unchanged — measured win) ----------------
#define STG_BYTES 32768
#define SM_GEMM   (3 * STG_BYTES)
#define NCHUNK    (GK / 64)

__device__ __forceinline__ void stage_issue(
    const __nv_bfloat16* __restrict__ A, const __nv_bfloat16* __restrict__ B,
    uint32_t smb, int s, int c, int m0, int n0, int tid)
{
#pragma unroll
    for (int q = 0; q < 4; q++) {
        int idx = q * 256 + tid;
        int row = idx >> 3;
        int c16 = idx & 7;
        uint32_t off = SWZ128(row * 128 + c16 * 16);
        const void* sA = (const void*)(A + (size_t)(m0 + row) * GK + c * 64 + c16 * 8);
        const void* sB = (const void*)(B + (size_t)(n0 + row) * GK + c * 64 + c16 * 8);
        CP16(smb + s * STG_BYTES + off, sA);
        CP16(smb + s * STG_BYTES + 16384 + off, sB);
    }
}

template <bool RELU>
__global__ __launch_bounds__(256, 2) void gemm_mma(
    const __nv_bfloat16* __restrict__ A, const __nv_bfloat16* __restrict__ B,
    const float* __restrict__ bias, float* __restrict__ C, int N)
{
    extern __shared__ char smem[];
    const uint32_t smb = smem_u32(smem);
    const int tid  = threadIdx.x;
    const int warp = tid >> 5;
    const int lane = tid & 31;
    const int m0 = blockIdx.y * 128;
    const int n0 = blockIdx.x * 128;
    const int wm = warp >> 1;
    const int wn = warp & 1;

    const int lrow = lane & 15;
    const int khi  = lane & 16;
    uint32_t a_rb[2], a_xm[2], b_rb[4], b_xm[4];
#pragma unroll
    for (int mi = 0; mi < 2; mi++) {
        int r = wm * 32 + mi * 16 + lrow;
        a_rb[mi] = r * 128;
        a_xm[mi] = (r << 4) & 0x70;
    }
#pragma unroll
    for (int nb = 0; nb < 4; nb++) {
        int r = wn * 64 + nb * 16 + lrow;
        b_rb[nb] = r * 128;
        b_xm[nb] = (r << 4) & 0x70;
    }

    float acc[2][8][4];
#pragma unroll
    for (int mi = 0; mi < 2; mi++)
#pragma unroll
        for (int ni = 0; ni < 8; ni++)
#pragma unroll
            for (int v = 0; v < 4; v++) acc[mi][ni][v] = 0.0f;

    stage_issue(A, B, smb, 0, 0, m0, n0, tid); CP_COMMIT();
    stage_issue(A, B, smb, 1, 1, m0, n0, tid); CP_COMMIT();
    stage_issue(A, B, smb, 2, 2, m0, n0, tid); CP_COMMIT();

    int s = 0;
    for (int c = 0; c < NCHUNK; c++) {
        CP_WAIT2();
        __syncthreads();
        const uint32_t sa = smb + s * STG_BYTES;
        const uint32_t sb = sa + 16384;

#pragma unroll
        for (int ks = 0; ks < 4; ks++) {
            const uint32_t col = ks * 32 + khi;
            uint32_t af[2][4];
#pragma unroll
            for (int mi = 0; mi < 2; mi++)
                LDSM4(af[mi][0], af[mi][1], af[mi][2], af[mi][3],
                      sa + a_rb[mi] + (col ^ a_xm[mi]));
            uint32_t bf_[4][4];
#pragma unroll
            for (int nb = 0; nb < 4; nb++)
                LDSM4(bf_[nb][0], bf_[nb][1], bf_[nb][2], bf_[nb][3],
                      sb + b_rb[nb] + (col ^ b_xm[nb]));
#pragma unroll
            for (int mi = 0; mi < 2; mi++)
#pragma unroll
                for (int nb = 0; nb < 4; nb++) {
                    MMA16816(acc[mi][nb * 2 + 0],
                             af[mi][0], af[mi][1], af[mi][2], af[mi][3],
                             bf_[nb][0], bf_[nb][2]);
                    MMA16816(acc[mi][nb * 2 + 1],
                             af[mi][0], af[mi][1], af[mi][2], af[mi][3],
                             bf_[nb][1], bf_[nb][3]);
                }
        }
        __syncthreads();
        if (c + 3 < NCHUNK)
            stage_issue(A, B, smb, s, c + 3, m0, n0, tid);
        CP_COMMIT();
        s = (s == 2) ? 0 : s + 1;
    }

#pragma unroll
    for (int mi = 0; mi < 2; mi++) {
        const int r = m0 + wm * 32 + mi * 16 + (lane >> 2);
#pragma unroll
        for (int ni = 0; ni < 8; ni++) {
            const int col = n0 + wn * 64 + ni * 8 + 2 * (lane & 3);
            const float2 bv = *(const float2*)&bias[col];
            float2 v0, v1;
            v0.x = acc[mi][ni][0] + bv.x;  v0.y = acc[mi][ni][1] + bv.y;
            v1.x = acc[mi][ni][2] + bv.x;  v1.y = acc[mi][ni][3] + bv.y;
            if (RELU) {
                v0.x = fmaxf(v0.x, 0.f); v0.y = fmaxf(v0.y, 0.f);
                v1.x = fmaxf(v1.x, 0.f); v1.y = fmaxf(v1.y, 0.f);
            }
            *(float2*)&C[(size_t)r * N + col] = v0;
            *(float2*)&C[(size_t)(r + 8) * N + col] = v1;
        }
    }
}

// ---------------- persistent HMMA GRU scan (natural order, EARLY-issue staging) ----
#define SC_CH    8
#define WB_OFF   0                 // W hi/lo tiles: 98304 B
#define HS_OFF   98304             // h staging 3-buf cp.async: 98304 B
#define GH_OFF   196608            // [64][26] fp32 = 6656
#define MSK_OFF  203264            // 64 fp32
#define SOUT_OFF 203520            // 512 fp32
#define SM_SCAN  205568

__device__ __forceinline__ void cp_hb(uint32_t smb, int buf,
                                      const float4* __restrict__ hb4, int c, int tid) {
#pragma unroll
    for (int r = 0; r < 6; r++) {
        int idx = r * 384 + tid;
        if (idx < 2048) {
            int term = idx >> 10, e = (idx >> 4) & 63, seg = idx & 15;
            CP16(smb + HS_OFF + buf * 32768 + term * 16384 + (seg >> 3) * 8192
                     + SWZ128(e * 128 + (seg & 7) * 16),
                 (const void*)(hb4 + e * 256 + term * 128 + c * 16 + seg));
        }
    }
}
__device__ __forceinline__ void gate_poll(int grp, unsigned tgt) {
    const volatile unsigned* p = (const volatile unsigned*)&g_cnt[grp];
    while (*p < tgt) __nanosleep(32);
}

__global__ __launch_bounds__(384) void scan_kernel(
    const float* __restrict__ done,
    const float* __restrict__ w_hh,
    const float* __restrict__ b_hh,
    __nv_bfloat16* __restrict__ bufA)
{
    extern __shared__ char smem[];
    const uint32_t smb = smem_u32(smem);
    float* gh   = (float*)(smem + GH_OFF);
    float* msk  = (float*)(smem + MSK_OFF);
    float* sOut = (float*)(smem + SOUT_OFF);

    const int tid  = threadIdx.x;
    const int wid  = tid >> 5;
    const int lane = tid & 31;
    const int mi   = wid & 3;
    const int ni   = wid >> 2;

    // ---- prologue: split w_hh slice to bf16 hi/lo SW128 B-tiles ----
#pragma unroll
    for (int g = 0; g < 8; g++) {
        int gidx = g * 384 + tid;
        int r = gidx >> 7;
        int k0 = (gidx & 127) * 8;
        const float* src = &w_hh[(size_t)((r >> 3) * HID + blockIdx.x * JPC + (r & 7)) * HID + k0];
        float4 v0 = *(const float4*)src;
        float4 v1 = *(const float4*)(src + 4);
        float f[8] = {v0.x, v0.y, v0.z, v0.w, v1.x, v1.y, v1.z, v1.w};
        unsigned short hi[8], lo[8];
#pragma unroll
        for (int q = 0; q < 8; q++) {
            __nv_bfloat16 h = __float2bfloat16(f[q]);
            hi[q] = *(unsigned short*)&h;
            __nv_bfloat16 l = __float2bfloat16(f[q] - __bfloat162float(h));
            lo[q] = *(unsigned short*)&l;
        }
        uint4 hv, lv;
        hv.x = hi[0] | (hi[1] << 16); hv.y = hi[2] | (hi[3] << 16);
        hv.z = hi[4] | (hi[5] << 16); hv.w = hi[6] | (hi[7] << 16);
        lv.x = lo[0] | (lo[1] << 16); lv.y = lo[2] | (lo[3] << 16);
        lv.z = lo[4] | (lo[5] << 16); lv.w = lo[6] | (lo[7] << 16);
        int c = k0 >> 7, sub = (k0 >> 6) & 1, colb = (k0 & 63) * 2;
        uint32_t off = c * 6144 + sub * 3072 + SWZ128(r * 128 + colb);
        *(uint4*)(smem + WB_OFF + off) = hv;
        *(uint4*)(smem + WB_OFF + 49152 + off) = lv;
    }

    // j-fast pair mapping
    const int env1 = tid >> 3, j1 = tid & 7;
    const int jg1  = blockIdx.x * JPC + j1;
    const bool has2 = (tid < 128);
    const int env2 = 48 + (tid >> 3);
    const float bR = b_hh[jg1];
    const float bZ = b_hh[HID + jg1];
    const float bN = b_hh[2 * HID + jg1];
    const int mygrp = blockIdx.x >> 4;

    // ldsm bases
    const int a_r  = mi * 16 + (lane & 15);
    const uint32_t a_rb = a_r * 128, a_xm = (a_r << 4) & 0x70;
    const uint32_t a_kh = lane & 16;
    const int b_r  = ni * 8 + (lane & 7);
    const uint32_t b_rb = b_r * 128, b_xm = (b_r << 4) & 0x70;
    const uint32_t b_cb = (lane >> 3) * 16;

    __syncthreads();   // w tiles ready

    for (int t = 0; t < TSTEPS; t++) {
        const int par = t & 1;
        const float4* __restrict__ hb4 = (const float4*)g_hb[par];
        const unsigned short* __restrict__ hbu = (const unsigned short*)g_hb[par];
        __nv_bfloat16* __restrict__ hb_out = g_hb[par ^ 1];
        const unsigned tgt = 16u * (unsigned)t;

        if (tid < 64) msk[tid] = 1.0f - done[t * NENV + tid];

        // batched gate preload: one vectorized read of all 8 counters
        unsigned okmask = 0xFF;
        if (t > 0) {
            uint4 c0 = __ldcv((const uint4*)&g_cnt[0]);
            uint4 c1 = __ldcv((const uint4*)&g_cnt[4]);
            okmask = (unsigned)(c0.x >= tgt)       | ((unsigned)(c0.y >= tgt) << 1)
                   | ((unsigned)(c0.z >= tgt) << 2) | ((unsigned)(c0.w >= tgt) << 3)
                   | ((unsigned)(c1.x >= tgt) << 4) | ((unsigned)(c1.y >= tgt) << 5)
                   | ((unsigned)(c1.z >= tgt) << 6) | ((unsigned)(c1.w >= tgt) << 7);
        }

        // epilogue operand prefetch (own-slice cols: no gate needed)
        const float* gib1 = g_gi + ((size_t)t * NENV + env1) * HID3 + jg1;
        const float gr1 = __ldg(gib1), gz1 = __ldg(gib1 + HID), gn1 = __ldg(gib1 + 2 * HID);
        unsigned short h1a = __ldcg(&hbu[env1 * 2048 + jg1]);
        unsigned short h1b = __ldcg(&hbu[env1 * 2048 + 1024 + jg1]);
        float gr2 = 0, gz2 = 0, gn2 = 0;
        unsigned short h2a = 0, h2b = 0;
        if (has2) {
            const float* gib2 = g_gi + ((size_t)t * NENV + env2) * HID3 + jg1;
            gr2 = __ldg(gib2); gz2 = __ldg(gib2 + HID); gn2 = __ldg(gib2 + 2 * HID);
            h2a = __ldcg(&hbu[env2 * 2048 + jg1]);
            h2b = __ldcg(&hbu[env2 * 2048 + 1024 + jg1]);
        }

        // stage chunks 0,1 (gated on their producer groups)
        if (!(okmask & 1u)) gate_poll(0, tgt);
        cp_hb(smb, 0, hb4, 0, tid); CP_COMMIT();
        if (!(okmask & 2u)) gate_poll(1, tgt);
        cp_hb(smb, 1, hb4, 1, tid); CP_COMMIT();

        float acc[4] = {0.f, 0.f, 0.f, 0.f};
        int buf = 0;

        for (int c = 0; c < SC_CH; c++) {
            CP_WAIT1();
            __syncthreads();

            // EARLY-issue chunk c+2 into buf (buf+2)%3 — that buffer held chunk
            // c-1, whose reads were sealed by the sync above. The gate latency
            // and cp flight now overlap the compute phase below.
            if (c + 2 < SC_CH) {
                if (!((okmask >> (c + 2)) & 1u)) gate_poll(c + 2, tgt);
                cp_hb(smb, (buf + 2) % 3, hb4, c + 2, tid);
            }
            CP_COMMIT();

            const uint32_t hbase = smb + HS_OFF + buf * 32768;
            const uint32_t wbase = smb + WB_OFF + c * 6144;
#pragma unroll
            for (int sub = 0; sub < 2; sub++) {
                const uint32_t hHi = hbase + sub * 8192;
                const uint32_t hLo = hHi + 16384;
                const uint32_t wH  = wbase + sub * 3072;
                const uint32_t wL  = wH + 49152;
#pragma unroll
                for (int k2 = 0; k2 < 2; k2++) {
                    uint32_t ah0[4], ah1[4], al0[4], al1[4], bh[4], bl[4];
                    const uint32_t ca = (k2 * 2) * 32 + a_kh;
                    const uint32_t cb = (k2 * 2 + 1) * 32 + a_kh;
                    LDSM4(ah0[0], ah0[1], ah0[2], ah0[3], hHi + a_rb + (ca ^ a_xm));
                    LDSM4(ah1[0], ah1[1], ah1[2], ah1[3], hHi + a_rb + (cb ^ a_xm));
                    LDSM4(al0[0], al0[1], al0[2], al0[3], hLo + a_rb + (ca ^ a_xm));
                    LDSM4(al1[0], al1[1], al1[2], al1[3], hLo + a_rb + (cb ^ a_xm));
                    const uint32_t wc = k2 * 64 + b_cb;
                    LDSM4(bh[0], bh[1], bh[2], bh[3], wH + b_rb + (wc ^ b_xm));
                    LDSM4(bl[0], bl[1], bl[2], bl[3], wL + b_rb + (wc ^ b_xm));
                    MMA16816(acc, ah0[0], ah0[1], ah0[2], ah0[3], bh[0], bh[1]);
                    MMA16816(acc, ah1[0], ah1[1], ah1[2], ah1[3], bh[2], bh[3]);
                    MMA16816(acc, ah0[0], ah0[1], ah0[2], ah0[3], bl[0], bl[1]);
                    MMA16816(acc, ah1[0], ah1[1], ah1[2], ah1[3], bl[2], bl[3]);
                    MMA16816(acc, al0[0], al0[1], al0[2], al0[3], bh[0], bh[1]);
                    MMA16816(acc, al1[0], al1[1], al1[2], al1[3], bh[2], bh[3]);
                }
            }
            buf = (buf == 2) ? 0 : buf + 1;
        }

        // scatter accumulators to gh[env][26]
        {
            const int er = mi * 16 + (lane >> 2);
            const int nc = ni * 8 + (lane & 3) * 2;
            *(float2*)&gh[er * 26 + nc] = make_float2(acc[0], acc[1]);
            *(float2*)&gh[(er + 8) * 26 + nc] = make_float2(acc[2], acc[3]);
        }
        __syncthreads();

        // ---- phase 1: gates -> sOut ----
        {
            const float m = msk[env1];
            const float hp = __bfloat162float(*(__nv_bfloat16*)&h1a)
                           + __bfloat162float(*(__nv_bfloat16*)&h1b);
            const float r = sigmoidf_(gr1 + m * gh[env1 * 26 + j1] + bR);
            const float z = sigmoidf_(gz1 + m * gh[env1 * 26 + 8 + j1] + bZ);
            const float n = tanhf(gn1 + r * (m * gh[env1 * 26 + 16 + j1] + bN));
            sOut[tid] = (1.0f - z) * n + z * (hp * m);
        }
        if (has2) {
            const float m = msk[env2];
            const float hp = __bfloat162float(*(__nv_bfloat16*)&h2a)
                           + __bfloat162float(*(__nv_bfloat16*)&h2b);
            const float r = sigmoidf_(gr2 + m * gh[env2 * 26 + j1] + bR);
            const float z = sigmoidf_(gz2 + m * gh[env2 * 26 + 8 + j1] + bZ);
            const float n = tanhf(gn2 + r * (m * gh[env2 * 26 + 16 + j1] + bN));
            sOut[384 + tid] = (1.0f - z) * n + z * (hp * m);
        }
        __syncthreads();

        // ---- phase 2: coalesced uint4 stores ----
        uint4 hv = {0, 0, 0, 0}, lv = {0, 0, 0, 0};
        if (tid < 64) {
            unsigned short hi[8], lo[8];
#pragma unroll
            for (int jj = 0; jj < 8; jj++) {
                float v = sOut[tid * 8 + jj];
                __nv_bfloat16 h = __float2bfloat16(v);
                hi[jj] = *(unsigned short*)&h;
                __nv_bfloat16 l = __float2bfloat16(v - __bfloat162float(h));
                lo[jj] = *(unsigned short*)&l;
            }
            hv.x = hi[0] | (hi[1] << 16); hv.y = hi[2] | (hi[3] << 16);
            hv.z = hi[4] | (hi[5] << 16); hv.w = hi[6] | (hi[7] << 16);
            lv.x = lo[0] | (lo[1] << 16); lv.y = lo[2] | (lo[3] << 16);
            lv.z = lo[4] | (lo[5] << 16); lv.w = lo[6] | (lo[7] << 16);
            __stcg((float4*)&hb_out[tid * 2048 + blockIdx.x * JPC], *(float4*)&hv);
            __stcg((float4*)&hb_out[tid * 2048 + 1024 + blockIdx.x * JPC], *(float4*)&lv);
        }

        // release: hb stores visible, then bump group counter
        __threadfence();
        __syncthreads();
        if (t + 1 < TSTEPS && tid == 0) atomicAdd(&g_cnt[mygrp], 1u);

        // bufA stores: off the critical path (consumed only after kernel ends)
        if (tid < 64) {
            __nv_bfloat16* arow = bufA + ((size_t)t * NENV + tid) * GK + blockIdx.x * JPC;
            __stcg((float4*)&arow[0], *(float4*)&hv);
            __stcg((float4*)&arow[HID], *(float4*)&hv);
            __stcg((float4*)&arow[2 * HID], *(float4*)&lv);
        }
    }
}

// ---------------- launch ----------------
extern "C" void kernel_launch(void* const* d_in, const int* in_sizes, int n_in,
                              void* d_out, int out_size)
{
    const float* x     = (const float*)d_in[0];
    const float* hxs   = (const float*)d_in[1];
    const float* done  = (const float*)d_in[2];
    const float* w_ih  = (const float*)d_in[3];
    const float* w_hh  = (const float*)d_in[4];
    const float* b_ih  = (const float*)d_in[5];
    const float* b_hh  = (const float*)d_in[6];
    const float* w_out = (const float*)d_in[7];
    const float* b_out = (const float*)d_in[8];
    float* out = (float*)d_out;

    float* gi_p = nullptr;
    __nv_bfloat16 *bA = nullptr, *bB = nullptr;
    cudaGetSymbolAddress((void**)&gi_p, g_gi);
    cudaGetSymbolAddress((void**)&bA, g_bufA);
    cudaGetSymbolAddress((void**)&bB, g_bufB);

    const int M = TSTEPS * NENV;   // 8192

    cudaFuncSetAttribute(scan_kernel,
                         cudaFuncAttributeMaxDynamicSharedMemorySize, SM_SCAN);
    cudaFuncSetAttribute(gemm_mma<false>,
                         cudaFuncAttributeMaxDynamicSharedMemorySize, SM_GEMM);
    cudaFuncSetAttribute(gemm_mma<true>,
                         cudaFuncAttributeMaxDynamicSharedMemorySize, SM_GEMM);

    init_kernel<<<(NENV * HID + 255) / 256, 256>>>(hxs);

    // gi = x @ w_ih^T + b_ih
    split_bf16<0><<<(M * HID / 8 + 255) / 256, 256>>>(x, bA, M * HID / 8);
    split_bf16<1><<<(HID3 * HID / 8 + 255) / 256, 256>>>(w_ih, bB, HID3 * HID / 8);
    gemm_mma<false><<<dim3(HID3 / 128, M / 128), 256, SM_GEMM>>>(bA, bB, b_ih, gi_p, HID3);

    // 128-step persistent HMMA scan (early-issue staging, writes ys-split into bA)
    scan_kernel<<<G, 384, SM_SCAN>>>(done, w_hh, b_hh, bA);

    // out = relu(ys @ w_out^T + b_out)
    split_bf16<1><<<(HID * HID / 8 + 255) / 256, 256>>>(w_out, bB, HID * HID / 8);
    gemm_mma<true><<<dim3(HID / 128, M / 128), 256, SM_GEMM>>>(bA, bB, b_out, out, HID);

    copy_hlast_kernel<<<(NENV * HID + 255) / 256, 256>>>(out + (size_t)M * HID);
}

// round 17
// speedup vs baseline: 1.0929x; 1.0929x over previous
#include <cuda_runtime.h>
#include <cuda_bf16.h>
#include <math.h>
#include <stdint.h>

#define TSTEPS 128
#define NENV   64
#define HID    1024
#define HID3   (3 * HID)
#define GK     3072

#define G      128      // scan CTAs (j-slices of 8)
#define JPC    8

// ---------------- scratch ----------------
__device__ float g_gi[TSTEPS * NENV * HID3];            // 96 MB
__device__ __nv_bfloat16 g_hb[2][NENV * 2048];          // h split: per env [hi(1024) | lo(1024)]
__device__ __align__(16) unsigned g_cnt[8];             // producer-group step counters
__device__ __nv_bfloat16 g_bufA[TSTEPS * NENV * GK];    // split A (x, then ys written by scan)
__device__ __nv_bfloat16 g_bufB[HID3 * GK];             // split B (w_ih, then w_out)

// ---------------- ptx helpers (sm_103-safe) ----------------
__device__ __forceinline__ uint32_t smem_u32(const void* p) {
    uint32_t a;
    asm("{ .reg .u64 t; cvta.to.shared.u64 t, %1; cvt.u32.u64 %0, t; }" : "=r"(a) : "l"(p));
    return a;
}
#define SWZ128(x) ((x) ^ (((x) >> 3) & 0x70))

#define CP16(dst, src) \
    asm volatile("cp.async.cg.shared.global [%0], [%1], 16;" :: "r"(dst), "l"(src))
#define CP_COMMIT() asm volatile("cp.async.commit_group;" ::: "memory")
#define CP_WAIT1()  asm volatile("cp.async.wait_group 1;" ::: "memory")
#define CP_WAIT2()  asm volatile("cp.async.wait_group 2;" ::: "memory")

#define LDSM4(r0, r1, r2, r3, addr) \
    asm volatile("ldmatrix.sync.aligned.m8n8.x4.shared.b16 {%0,%1,%2,%3}, [%4];" \
        : "=r"(r0), "=r"(r1), "=r"(r2), "=r"(r3) : "r"(addr))

#define MMA16816(d, a0, a1, a2, a3, b0, b1) \
    asm volatile("mma.sync.aligned.m16n8k16.row.col.f32.bf16.bf16.f32 " \
        "{%0,%1,%2,%3}, {%4,%5,%6,%7}, {%8,%9}, {%0,%1,%2,%3};" \
        : "+f"((d)[0]), "+f"((d)[1]), "+f"((d)[2]), "+f"((d)[3]) \
        : "r"(a0), "r"(a1), "r"(a2), "r"(a3), "r"(b0), "r"(b1))

__device__ __forceinline__ float sigmoidf_(float x) { return 1.0f / (1.0f + expf(-x)); }

// ---------------- init / split ----------------
__global__ void init_kernel(const float* __restrict__ hxs) {
    int i = blockIdx.x * blockDim.x + threadIdx.x;
    if (i < 8) g_cnt[i] = 0;
    if (i < NENV * HID) {
        float v = hxs[i];
        int env = i >> 10, k = i & 1023;
        __nv_bfloat16 hi = __float2bfloat16(v);
        __nv_bfloat16 lo = __float2bfloat16(v - __bfloat162float(hi));
        g_hb[0][env * 2048 + k] = hi;
        g_hb[0][env * 2048 + 1024 + k] = lo;
    }
}

// Vectorized split: 8 consecutive k per thread.
// MODE 0 (A operand): [hi, hi, lo]   MODE 1 (B operand): [hi, lo, hi]
template <int MODE>
__global__ void split_bf16(const float* __restrict__ src,
                           __nv_bfloat16* __restrict__ dst, int total8) {
    int i = blockIdx.x * blockDim.x + threadIdx.x;   // one unit = 8 elems
    if (i >= total8) return;
    int m = i >> 7;               // / (HID/8)
    int k8 = (i & 127) * 8;
    const float* s = src + (size_t)m * HID + k8;
    float4 v0 = *(const float4*)s;
    float4 v1 = *(const float4*)(s + 4);
    float f[8] = {v0.x, v0.y, v0.z, v0.w, v1.x, v1.y, v1.z, v1.w};
    unsigned short hi[8], lo[8];
#pragma unroll
    for (int q = 0; q < 8; q++) {
        __nv_bfloat16 h = __float2bfloat16(f[q]);
        hi[q] = *(unsigned short*)&h;
        __nv_bfloat16 l = __float2bfloat16(f[q] - __bfloat162float(h));
        lo[q] = *(unsigned short*)&l;
    }
    uint4 hv, lv;
    hv.x = hi[0] | (hi[1] << 16); hv.y = hi[2] | (hi[3] << 16);
    hv.z = hi[4] | (hi[5] << 16); hv.w = hi[6] | (hi[7] << 16);
    lv.x = lo[0] | (lo[1] << 16); lv.y = lo[2] | (lo[3] << 16);
    lv.z = lo[4] | (lo[5] << 16); lv.w = lo[6] | (lo[7] << 16);
    __nv_bfloat16* row = dst + (size_t)m * GK + k8;
    if (MODE == 0) {
        *(uint4*)&row[0] = hv; *(uint4*)&row[HID] = hv; *(uint4*)&row[2 * HID] = lv;
    } else {
        *(uint4*)&row[0] = hv; *(uint4*)&row[HID] = lv; *(uint4*)&row[2 * HID] = hv;
    }
}

// ---------------- mma.sync bf16 GEMM (unchanged — measured win) ----------------
#define STG_BYTES 32768
#define SM_GEMM   (3 * STG_BYTES)
#define NCHUNK    (GK / 64)

__device__ __forceinline__ void stage_issue(
    const __nv_bfloat16* __restrict__ A, const __nv_bfloat16* __restrict__ B,
    uint32_t smb, int s, int c, int m0, int n0, int tid)
{
#pragma unroll
    for (int q = 0; q < 4; q++) {
        int idx = q * 256 + tid;
        int row = idx >> 3;
        int c16 = idx & 7;
        uint32_t off = SWZ128(row * 128 + c16 * 16);
        const void* sA = (const void*)(A + (size_t)(m0 + row) * GK + c * 64 + c16 * 8);
        const void* sB = (const void*)(B + (size_t)(n0 + row) * GK + c * 64 + c16 * 8);
        CP16(smb + s * STG_BYTES + off, sA);
        CP16(smb + s * STG_BYTES + 16384 + off, sB);
    }
}

template <bool RELU>
__global__ __launch_bounds__(256, 2) void gemm_mma(
    const __nv_bfloat16* __restrict__ A, const __nv_bfloat16* __restrict__ B,
    const float* __restrict__ bias, float* __restrict__ C, int N)
{
    extern __shared__ char smem[];
    const uint32_t smb = smem_u32(smem);
    const int tid  = threadIdx.x;
    const int warp = tid >> 5;
    const int lane = tid & 31;
    const int m0 = blockIdx.y * 128;
    const int n0 = blockIdx.x * 128;
    const int wm = warp >> 1;
    const int wn = warp & 1;

    const int lrow = lane & 15;
    const int khi  = lane & 16;
    uint32_t a_rb[2], a_xm[2], b_rb[4], b_xm[4];
#pragma unroll
    for (int mi = 0; mi < 2; mi++) {
        int r = wm * 32 + mi * 16 + lrow;
        a_rb[mi] = r * 128;
        a_xm[mi] = (r << 4) & 0x70;
    }
#pragma unroll
    for (int nb = 0; nb < 4; nb++) {
        int r = wn * 64 + nb * 16 + lrow;
        b_rb[nb] = r * 128;
        b_xm[nb] = (r << 4) & 0x70;
    }

    float acc[2][8][4];
#pragma unroll
    for (int mi = 0; mi < 2; mi++)
#pragma unroll
        for (int ni = 0; ni < 8; ni++)
#pragma unroll
            for (int v = 0; v < 4; v++) acc[mi][ni][v] = 0.0f;

    stage_issue(A, B, smb, 0, 0, m0, n0, tid); CP_COMMIT();
    stage_issue(A, B, smb, 1, 1, m0, n0, tid); CP_COMMIT();
    stage_issue(A, B, smb, 2, 2, m0, n0, tid); CP_COMMIT();

    int s = 0;
    for (int c = 0; c < NCHUNK; c++) {
        CP_WAIT2();
        __syncthreads();
        const uint32_t sa = smb + s * STG_BYTES;
        const uint32_t sb = sa + 16384;

#pragma unroll
        for (int ks = 0; ks < 4; ks++) {
            const uint32_t col = ks * 32 + khi;
            uint32_t af[2][4];
#pragma unroll
            for (int mi = 0; mi < 2; mi++)
                LDSM4(af[mi][0], af[mi][1], af[mi][2], af[mi][3],
                      sa + a_rb[mi] + (col ^ a_xm[mi]));
            uint32_t bf_[4][4];
#pragma unroll
            for (int nb = 0; nb < 4; nb++)
                LDSM4(bf_[nb][0], bf_[nb][1], bf_[nb][2], bf_[nb][3],
                      sb + b_rb[nb] + (col ^ b_xm[nb]));
#pragma unroll
            for (int mi = 0; mi < 2; mi++)
#pragma unroll
                for (int nb = 0; nb < 4; nb++) {
                    MMA16816(acc[mi][nb * 2 + 0],
                             af[mi][0], af[mi][1], af[mi][2], af[mi][3],
                             bf_[nb][0], bf_[nb][2]);
                    MMA16816(acc[mi][nb * 2 + 1],
                             af[mi][0], af[mi][1], af[mi][2], af[mi][3],
                             bf_[nb][1], bf_[nb][3]);
                }
        }
        __syncthreads();
        if (c + 3 < NCHUNK)
            stage_issue(A, B, smb, s, c + 3, m0, n0, tid);
        CP_COMMIT();
        s = (s == 2) ? 0 : s + 1;
    }

#pragma unroll
    for (int mi = 0; mi < 2; mi++) {
        const int r = m0 + wm * 32 + mi * 16 + (lane >> 2);
#pragma unroll
        for (int ni = 0; ni < 8; ni++) {
            const int col = n0 + wn * 64 + ni * 8 + 2 * (lane & 3);
            const float2 bv = *(const float2*)&bias[col];
            float2 v0, v1;
            v0.x = acc[mi][ni][0] + bv.x;  v0.y = acc[mi][ni][1] + bv.y;
            v1.x = acc[mi][ni][2] + bv.x;  v1.y = acc[mi][ni][3] + bv.y;
            if (RELU) {
                v0.x = fmaxf(v0.x, 0.f); v0.y = fmaxf(v0.y, 0.f);
                v1.x = fmaxf(v1.x, 0.f); v1.y = fmaxf(v1.y, 0.f);
            }
            *(float2*)&C[(size_t)r * N + col] = v0;
            *(float2*)&C[(size_t)(r + 8) * N + col] = v1;
        }
    }
}

// ---------------- persistent HMMA GRU scan (R15 config: natural order, end-issue) ----
#define SC_CH    8
#define WB_OFF   0                 // W hi/lo tiles: 98304 B
#define HS_OFF   98304             // h staging 3-buf cp.async: 98304 B
#define GH_OFF   196608            // [64][26] fp32 = 6656
#define MSK_OFF  203264            // 64 fp32
#define SOUT_OFF 203520            // 512 fp32
#define SM_SCAN  205568

__device__ __forceinline__ void cp_hb(uint32_t smb, int buf,
                                      const float4* __restrict__ hb4, int c, int tid) {
#pragma unroll
    for (int r = 0; r < 6; r++) {
        int idx = r * 384 + tid;
        if (idx < 2048) {
            int term = idx >> 10, e = (idx >> 4) & 63, seg = idx & 15;
            CP16(smb + HS_OFF + buf * 32768 + term * 16384 + (seg >> 3) * 8192
                     + SWZ128(e * 128 + (seg & 7) * 16),
                 (const void*)(hb4 + e * 256 + term * 128 + c * 16 + seg));
        }
    }
}
__device__ __forceinline__ void gate_poll(int grp, unsigned tgt) {
    const volatile unsigned* p = (const volatile unsigned*)&g_cnt[grp];
    while (*p < tgt) __nanosleep(32);
}

__global__ __launch_bounds__(384) void scan_kernel(
    const float* __restrict__ done,
    const float* __restrict__ w_hh,
    const float* __restrict__ b_hh,
    __nv_bfloat16* __restrict__ bufA,
    float* __restrict__ hlast)
{
    extern __shared__ char smem[];
    const uint32_t smb = smem_u32(smem);
    float* gh   = (float*)(smem + GH_OFF);
    float* msk  = (float*)(smem + MSK_OFF);
    float* sOut = (float*)(smem + SOUT_OFF);

    const int tid  = threadIdx.x;
    const int wid  = tid >> 5;
    const int lane = tid & 31;
    const int mi   = wid & 3;
    const int ni   = wid >> 2;

    // ---- prologue: split w_hh slice to bf16 hi/lo SW128 B-tiles ----
#pragma unroll
    for (int g = 0; g < 8; g++) {
        int gidx = g * 384 + tid;
        int r = gidx >> 7;
        int k0 = (gidx & 127) * 8;
        const float* src = &w_hh[(size_t)((r >> 3) * HID + blockIdx.x * JPC + (r & 7)) * HID + k0];
        float4 v0 = *(const float4*)src;
        float4 v1 = *(const float4*)(src + 4);
        float f[8] = {v0.x, v0.y, v0.z, v0.w, v1.x, v1.y, v1.z, v1.w};
        unsigned short hi[8], lo[8];
#pragma unroll
        for (int q = 0; q < 8; q++) {
            __nv_bfloat16 h = __float2bfloat16(f[q]);
            hi[q] = *(unsigned short*)&h;
            __nv_bfloat16 l = __float2bfloat16(f[q] - __bfloat162float(h));
            lo[q] = *(unsigned short*)&l;
        }
        uint4 hv, lv;
        hv.x = hi[0] | (hi[1] << 16); hv.y = hi[2] | (hi[3] << 16);
        hv.z = hi[4] | (hi[5] << 16); hv.w = hi[6] | (hi[7] << 16);
        lv.x = lo[0] | (lo[1] << 16); lv.y = lo[2] | (lo[3] << 16);
        lv.z = lo[4] | (lo[5] << 16); lv.w = lo[6] | (lo[7] << 16);
        int c = k0 >> 7, sub = (k0 >> 6) & 1, colb = (k0 & 63) * 2;
        uint32_t off = c * 6144 + sub * 3072 + SWZ128(r * 128 + colb);
        *(uint4*)(smem + WB_OFF + off) = hv;
        *(uint4*)(smem + WB_OFF + 49152 + off) = lv;
    }

    // j-fast pair mapping
    const int env1 = tid >> 3, j1 = tid & 7;
    const int jg1  = blockIdx.x * JPC + j1;
    const bool has2 = (tid < 128);
    const int env2 = 48 + (tid >> 3);
    const float bR = b_hh[jg1];
    const float bZ = b_hh[HID + jg1];
    const float bN = b_hh[2 * HID + jg1];
    const int mygrp = blockIdx.x >> 4;

    // ldsm bases
    const int a_r  = mi * 16 + (lane & 15);
    const uint32_t a_rb = a_r * 128, a_xm = (a_r << 4) & 0x70;
    const uint32_t a_kh = lane & 16;
    const int b_r  = ni * 8 + (lane & 7);
    const uint32_t b_rb = b_r * 128, b_xm = (b_r << 4) & 0x70;
    const uint32_t b_cb = (lane >> 3) * 16;

    __syncthreads();   // w tiles ready

    for (int t = 0; t < TSTEPS; t++) {
        const int par = t & 1;
        const float4* __restrict__ hb4 = (const float4*)g_hb[par];
        const unsigned short* __restrict__ hbu = (const unsigned short*)g_hb[par];
        __nv_bfloat16* __restrict__ hb_out = g_hb[par ^ 1];
        const unsigned tgt = 16u * (unsigned)t;

        if (tid < 64) msk[tid] = 1.0f - done[t * NENV + tid];

        // batched gate preload: one vectorized read of all 8 counters
        unsigned okmask = 0xFF;
        if (t > 0) {
            uint4 c0 = __ldcv((const uint4*)&g_cnt[0]);
            uint4 c1 = __ldcv((const uint4*)&g_cnt[4]);
            okmask = (unsigned)(c0.x >= tgt)       | ((unsigned)(c0.y >= tgt) << 1)
                   | ((unsigned)(c0.z >= tgt) << 2) | ((unsigned)(c0.w >= tgt) << 3)
                   | ((unsigned)(c1.x >= tgt) << 4) | ((unsigned)(c1.y >= tgt) << 5)
                   | ((unsigned)(c1.z >= tgt) << 6) | ((unsigned)(c1.w >= tgt) << 7);
        }

        // epilogue operand prefetch (own-slice cols: no gate needed)
        const float* gib1 = g_gi + ((size_t)t * NENV + env1) * HID3 + jg1;
        const float gr1 = __ldg(gib1), gz1 = __ldg(gib1 + HID), gn1 = __ldg(gib1 + 2 * HID);
        unsigned short h1a = __ldcg(&hbu[env1 * 2048 + jg1]);
        unsigned short h1b = __ldcg(&hbu[env1 * 2048 + 1024 + jg1]);
        float gr2 = 0, gz2 = 0, gn2 = 0;
        unsigned short h2a = 0, h2b = 0;
        if (has2) {
            const float* gib2 = g_gi + ((size_t)t * NENV + env2) * HID3 + jg1;
            gr2 = __ldg(gib2); gz2 = __ldg(gib2 + HID); gn2 = __ldg(gib2 + 2 * HID);
            h2a = __ldcg(&hbu[env2 * 2048 + jg1]);
            h2b = __ldcg(&hbu[env2 * 2048 + 1024 + jg1]);
        }

        // stage chunks 0,1 (gated on their producer groups)
        if (!(okmask & 1u)) gate_poll(0, tgt);
        cp_hb(smb, 0, hb4, 0, tid); CP_COMMIT();
        if (!(okmask & 2u)) gate_poll(1, tgt);
        cp_hb(smb, 1, hb4, 1, tid); CP_COMMIT();

        float acc[4] = {0.f, 0.f, 0.f, 0.f};
        int buf = 0;

        for (int c = 0; c < SC_CH; c++) {
            CP_WAIT1();
            __syncthreads();

            const uint32_t hbase = smb + HS_OFF + buf * 32768;
            const uint32_t wbase = smb + WB_OFF + c * 6144;
#pragma unroll
            for (int sub = 0; sub < 2; sub++) {
                const uint32_t hHi = hbase + sub * 8192;
                const uint32_t hLo = hHi + 16384;
                const uint32_t wH  = wbase + sub * 3072;
                const uint32_t wL  = wH + 49152;
#pragma unroll
                for (int k2 = 0; k2 < 2; k2++) {
                    uint32_t ah0[4], ah1[4], al0[4], al1[4], bh[4], bl[4];
                    const uint32_t ca = (k2 * 2) * 32 + a_kh;
                    const uint32_t cb = (k2 * 2 + 1) * 32 + a_kh;
                    LDSM4(ah0[0], ah0[1], ah0[2], ah0[3], hHi + a_rb + (ca ^ a_xm));
                    LDSM4(ah1[0], ah1[1], ah1[2], ah1[3], hHi + a_rb + (cb ^ a_xm));
                    LDSM4(al0[0], al0[1], al0[2], al0[3], hLo + a_rb + (ca ^ a_xm));
                    LDSM4(al1[0], al1[1], al1[2], al1[3], hLo + a_rb + (cb ^ a_xm));
                    const uint32_t wc = k2 * 64 + b_cb;
                    LDSM4(bh[0], bh[1], bh[2], bh[3], wH + b_rb + (wc ^ b_xm));
                    LDSM4(bl[0], bl[1], bl[2], bl[3], wL + b_rb + (wc ^ b_xm));
                    MMA16816(acc, ah0[0], ah0[1], ah0[2], ah0[3], bh[0], bh[1]);
                    MMA16816(acc, ah1[0], ah1[1], ah1[2], ah1[3], bh[2], bh[3]);
                    MMA16816(acc, ah0[0], ah0[1], ah0[2], ah0[3], bl[0], bl[1]);
                    MMA16816(acc, ah1[0], ah1[1], ah1[2], ah1[3], bl[2], bl[3]);
                    MMA16816(acc, al0[0], al0[1], al0[2], al0[3], bh[0], bh[1]);
                    MMA16816(acc, al1[0], al1[1], al1[2], al1[3], bh[2], bh[3]);
                }
            }
            if (c + 2 < SC_CH) {
                if (!((okmask >> (c + 2)) & 1u)) gate_poll(c + 2, tgt);
                cp_hb(smb, (buf + 2) % 3, hb4, c + 2, tid);
            }
            CP_COMMIT();
            buf = (buf == 2) ? 0 : buf + 1;
        }

        // scatter accumulators to gh[env][26]
        {
            const int er = mi * 16 + (lane >> 2);
            const int nc = ni * 8 + (lane & 3) * 2;
            *(float2*)&gh[er * 26 + nc] = make_float2(acc[0], acc[1]);
            *(float2*)&gh[(er + 8) * 26 + nc] = make_float2(acc[2], acc[3]);
        }
        __syncthreads();

        // ---- phase 1: gates -> sOut ----
        {
            const float m = msk[env1];
            const float hp = __bfloat162float(*(__nv_bfloat16*)&h1a)
                           + __bfloat162float(*(__nv_bfloat16*)&h1b);
            const float r = sigmoidf_(gr1 + m * gh[env1 * 26 + j1] + bR);
            const float z = sigmoidf_(gz1 + m * gh[env1 * 26 + 8 + j1] + bZ);
            const float n = tanhf(gn1 + r * (m * gh[env1 * 26 + 16 + j1] + bN));
            sOut[tid] = (1.0f - z) * n + z * (hp * m);
        }
        if (has2) {
            const float m = msk[env2];
            const float hp = __bfloat162float(*(__nv_bfloat16*)&h2a)
                           + __bfloat162float(*(__nv_bfloat16*)&h2b);
            const float r = sigmoidf_(gr2 + m * gh[env2 * 26 + j1] + bR);
            const float z = sigmoidf_(gz2 + m * gh[env2 * 26 + 8 + j1] + bZ);
            const float n = tanhf(gn2 + r * (m * gh[env2 * 26 + 16 + j1] + bN));
            sOut[384 + tid] = (1.0f - z) * n + z * (hp * m);
        }
        __syncthreads();

        // ---- phase 2: coalesced uint4 stores ----
        uint4 hv = {0, 0, 0, 0}, lv = {0, 0, 0, 0};
        if (tid < 64) {
            unsigned short hi[8], lo[8];
#pragma unroll
            for (int jj = 0; jj < 8; jj++) {
                float v = sOut[tid * 8 + jj];
                __nv_bfloat16 h = __float2bfloat16(v);
                hi[jj] = *(unsigned short*)&h;
                __nv_bfloat16 l = __float2bfloat16(v - __bfloat162float(h));
                lo[jj] = *(unsigned short*)&l;
            }
            hv.x = hi[0] | (hi[1] << 16); hv.y = hi[2] | (hi[3] << 16);
            hv.z = hi[4] | (hi[5] << 16); hv.w = hi[6] | (hi[7] << 16);
            lv.x = lo[0] | (lo[1] << 16); lv.y = lo[2] | (lo[3] << 16);
            lv.z = lo[4] | (lo[5] << 16); lv.w = lo[6] | (lo[7] << 16);
            __stcg((float4*)&hb_out[tid * 2048 + blockIdx.x * JPC], *(float4*)&hv);
            __stcg((float4*)&hb_out[tid * 2048 + 1024 + blockIdx.x * JPC], *(float4*)&lv);
        }

        // release: hb stores visible, then bump group counter
        __threadfence();
        __syncthreads();
        if (t + 1 < TSTEPS && tid == 0) atomicAdd(&g_cnt[mygrp], 1u);

        // bufA stores: off the critical path (consumed only after kernel ends)
        if (tid < 64) {
            __nv_bfloat16* arow = bufA + ((size_t)t * NENV + tid) * GK + blockIdx.x * JPC;
            __stcg((float4*)&arow[0], *(float4*)&hv);
            __stcg((float4*)&arow[HID], *(float4*)&hv);
            __stcg((float4*)&arow[2 * HID], *(float4*)&lv);
        }

        // final step: write h_last directly (exact fp32 from sOut)
        if (t == TSTEPS - 1 && tid < 64) {
            float4 o0 = *(float4*)&sOut[tid * 8];
            float4 o1 = *(float4*)&sOut[tid * 8 + 4];
            float* dst = hlast + (size_t)tid * HID + blockIdx.x * JPC;
            *(float4*)&dst[0] = o0;
            *(float4*)&dst[4] = o1;
        }
    }
}

// ---------------- launch ----------------
extern "C" void kernel_launch(void* const* d_in, const int* in_sizes, int n_in,
                              void* d_out, int out_size)
{
    const float* x     = (const float*)d_in[0];
    const float* hxs   = (const float*)d_in[1];
    const float* done  = (const float*)d_in[2];
    const float* w_ih  = (const float*)d_in[3];
    const float* w_hh  = (const float*)d_in[4];
    const float* b_ih  = (const float*)d_in[5];
    const float* b_hh  = (const float*)d_in[6];
    const float* w_out = (const float*)d_in[7];
    const float* b_out = (const float*)d_in[8];
    float* out = (float*)d_out;

    float* gi_p = nullptr;
    __nv_bfloat16 *bA = nullptr, *bB = nullptr;
    cudaGetSymbolAddress((void**)&gi_p, g_gi);
    cudaGetSymbolAddress((void**)&bA, g_bufA);
    cudaGetSymbolAddress((void**)&bB, g_bufB);

    const int M = TSTEPS * NENV;   // 8192

    cudaFuncSetAttribute(scan_kernel,
                         cudaFuncAttributeMaxDynamicSharedMemorySize, SM_SCAN);
    cudaFuncSetAttribute(gemm_mma<false>,
                         cudaFuncAttributeMaxDynamicSharedMemorySize, SM_GEMM);
    cudaFuncSetAttribute(gemm_mma<true>,
                         cudaFuncAttributeMaxDynamicSharedMemorySize, SM_GEMM);

    init_kernel<<<(NENV * HID + 255) / 256, 256>>>(hxs);

    // gi = x @ w_ih^T + b_ih
    split_bf16<0><<<(M * HID / 8 + 255) / 256, 256>>>(x, bA, M * HID / 8);
    split_bf16<1><<<(HID3 * HID / 8 + 255) / 256, 256>>>(w_ih, bB, HID3 * HID / 8);
    gemm_mma<false><<<dim3(HID3 / 128, M / 128), 256, SM_GEMM>>>(bA, bB, b_ih, gi_p, HID3);

    // 128-step persistent HMMA scan (R15 config; writes ys-split into bA and h_last into out)
    scan_kernel<<<G, 384, SM_SCAN>>>(done, w_hh, b_hh, bA, out + (size_t)M * HID);

    // out = relu(ys @ w_out^T + b_out)
    split_bf16<1><<<(HID * HID / 8 + 255) / 256, 256>>>(w_out, bB, HID * HID / 8);
    gemm_mma<true><<<dim3(HID / 128, M / 128), 256, SM_GEMM>>>(bA, bB, b_out, out, HID);
}